// round 9
// baseline (speedup 1.0000x reference)
#include <cuda_runtime.h>
#include <cuda_bf16.h>
#include <cuda_fp16.h>
#include <cstdint>

#define H 1024
#define W 1024
#define HID 256
#define C 3

typedef unsigned long long u64t;

// ---------------------------------------------------------------------------
// global scratch
// ---------------------------------------------------------------------------
__device__ __align__(16) __half g_fxh[H * HID];
__device__ __align__(16) __half g_fyh[W * HID];
// qw1 as fp16, SW128-swizzled K-major tiles. chunk c (k0=64c): 32KB at c*32768
__device__ __align__(16) unsigned char g_qpack[4 * 32768];

// ---------------- fast sine (scalar, branch kernel) ------------------------
__device__ __forceinline__ float fast_sin(float x) {
    const float INV_PI = 0.318309886183790671f;
    float k = rintf(x * INV_PI);
    float r = fmaf(-k, 3.14159274101257324f, x);
    r = fmaf(k, 8.74227765734758577e-8f, r);
    float s = r * r;
    float p = fmaf(s, 2.75573192e-6f, -1.98412698e-4f);
    p = fmaf(s, p, 8.33333333e-3f);
    p = fmaf(s, p, -1.66666667e-1f);
    float res = fmaf(s * r, p, r);
    int ki = (int)k;
    return (ki & 1) ? -res : res;
}

// ---------------- f32x2 packed helpers -------------------------------------
__device__ __forceinline__ u64t pk2(float lo, float hi) {
    u64t r;
    asm("mov.b64 %0, {%1, %2};" : "=l"(r)
        : "r"(__float_as_uint(lo)), "r"(__float_as_uint(hi)));
    return r;
}
__device__ __forceinline__ void upk2(u64t v, float& lo, float& hi) {
    uint32_t a, b;
    asm("mov.b64 {%0, %1}, %2;" : "=r"(a), "=r"(b) : "l"(v));
    lo = __uint_as_float(a);
    hi = __uint_as_float(b);
}
__device__ __forceinline__ u64t dup2(float v) { return pk2(v, v); }
__device__ __forceinline__ u64t f2fma(u64t a, u64t b, u64t c) {
    u64t r;
    asm("fma.rn.f32x2 %0, %1, %2, %3;" : "=l"(r) : "l"(a), "l"(b), "l"(c));
    return r;
}
__device__ __forceinline__ u64t f2add(u64t a, u64t b) {
    u64t r;
    asm("add.rn.f32x2 %0, %1, %2;" : "=l"(r) : "l"(a), "l"(b));
    return r;
}
__device__ __forceinline__ u64t f2mul(u64t a, u64t b) {
    u64t r;
    asm("mul.rn.f32x2 %0, %1, %2;" : "=l"(r) : "l"(a), "l"(b));
    return r;
}

// ---------------- misc PTX helpers -----------------------------------------
__device__ __forceinline__ uint32_t smem_u32(const void* p) {
    uint32_t a;
    asm("{ .reg .u64 t; cvta.to.shared.u64 t, %1; cvt.u32.u64 %0, t; }"
        : "=r"(a) : "l"(p));
    return a;
}
__device__ __forceinline__ void ldsm_x4(uint32_t* r, uint32_t addr) {
    asm volatile("ldmatrix.sync.aligned.m8n8.x4.shared.b16 {%0,%1,%2,%3}, [%4];"
                 : "=r"(r[0]), "=r"(r[1]), "=r"(r[2]), "=r"(r[3]) : "r"(addr));
}
__device__ __forceinline__ void mma_f16(float* c, const uint32_t* a,
                                        const uint32_t* b) {
    asm volatile(
        "mma.sync.aligned.m16n8k16.row.col.f32.f16.f16.f32 "
        "{%0,%1,%2,%3}, {%4,%5,%6,%7}, {%8,%9}, {%0,%1,%2,%3};"
        : "+f"(c[0]), "+f"(c[1]), "+f"(c[2]), "+f"(c[3])
        : "r"(a[0]), "r"(a[1]), "r"(a[2]), "r"(a[3]), "r"(b[0]), "r"(b[1]));
}
#define CP_ASYNC16(dst, src) \
    asm volatile("cp.async.cg.shared.global [%0], [%1], 16;" \
                 :: "r"(dst), "l"(src))
#define CP_COMMIT()  asm volatile("cp.async.commit_group;")
#define CP_WAIT0()   asm volatile("cp.async.wait_group 0;" ::: "memory")
#define CP_WAIT1()   asm volatile("cp.async.wait_group 1;" ::: "memory")

__device__ __forceinline__ uint32_t packh2(float hi, float lo) {
    uint32_t r;
    asm("cvt.rn.f16x2.f32 %0, %1, %2;" : "=r"(r) : "f"(hi), "f"(lo));
    return r;
}
__device__ __forceinline__ uint32_t hmul2(uint32_t a, uint32_t b) {
    uint32_t r;
    asm("mul.rn.f16x2 %0, %1, %2;" : "=r"(r) : "r"(a), "r"(b));
    return r;
}

// ---------------- kernel 0: pack+swizzle qw1 to fp16 -----------------------
__global__ void pack_qw1_kernel(const float* __restrict__ qw1) {
    int idx = blockIdx.x * 256 + threadIdx.x;
    int n = idx >> 7;
    int kw = idx & 127;
    int k = kw * 2;
    int cch = k >> 6;
    int kk = k & 63;
    float w0 = qw1[n * HID + k];
    float w1 = qw1[n * HID + k + 1];
    uint32_t hw = packh2(w1, w0);
    uint32_t off = ((n >> 3) << 10) + ((n & 7) << 7) + kk * 2;
    uint32_t sw = off ^ ((off >> 3) & 0x70);
    *(uint32_t*)(g_qpack + cch * 32768 + sw) = hw;
}

// ---------------- kernel 1: branch + premerge (fp16 outputs) ---------------
__device__ __forceinline__ void dense_layer(
    const float (*hin)[HID], float (*hout)[HID],
    const float* __restrict__ pw, const float* __restrict__ pb, int t)
{
    float acc[16];
    float bias = pb[t];
#pragma unroll
    for (int r = 0; r < 16; r++) acc[r] = bias;
    const float4* pw4 = (const float4*)pw;
#pragma unroll 4
    for (int k4 = 0; k4 < HID / 4; k4++) {
        float4 w4 = pw4[t * (HID / 4) + k4];
#pragma unroll
        for (int r = 0; r < 16; r++) {
            float4 hv = *(const float4*)&hin[r][k4 * 4];
            acc[r] = fmaf(hv.x, w4.x, acc[r]);
            acc[r] = fmaf(hv.y, w4.y, acc[r]);
            acc[r] = fmaf(hv.z, w4.z, acc[r]);
            acc[r] = fmaf(hv.w, w4.w, acc[r]);
        }
    }
#pragma unroll
    for (int r = 0; r < 16; r++) hout[r][t] = fast_sin(acc[r]);
}

__global__ void branch_kernel(
    const float* __restrict__ x, const float* __restrict__ y,
    const float* __restrict__ bw0, const float* __restrict__ bb0,
    const float* __restrict__ bw1, const float* __restrict__ bb1,
    const float* __restrict__ pw1, const float* __restrict__ pb1,
    const float* __restrict__ pw2, const float* __restrict__ pb2)
{
    int axis = blockIdx.y;
    const float* coord = axis ? y : x;
    const float* bw = axis ? bw1 : bw0;
    const float* bb = axis ? bb1 : bb0;
    __half* outf = axis ? g_fyh : g_fxh;
    int r0 = blockIdx.x * 16;
    int t = threadIdx.x;

    __shared__ __align__(16) float hA[16][HID];
    __shared__ __align__(16) float hB[16][HID];

    float w = bw[t], b = bb[t];
#pragma unroll
    for (int r = 0; r < 16; r++)
        hA[r][t] = fast_sin(fmaf(coord[r0 + r], w, b));
    __syncthreads();
    dense_layer(hA, hB, pw1, pb1, t);
    __syncthreads();
    dense_layer(hB, hA, pw2, pb2, t);
    __syncthreads();
#pragma unroll
    for (int r = 0; r < 16; r++)
        outf[(r0 + r) * HID + t] = __float2half_rn(hA[r][t]);
}

// ---------------- kernel 2: M=64 tile, pipelined epilogue ------------------
// grid (16, 128): i0 = bx*64, j in [by*8, by*8+8). 512 threads = 16 warps,
// warp tile 16(m) x 64(n). B (128KB) + fx tile (32KB) SMEM-resident.
// Per j: 4 K-chunk steps. Epilogue of j-1 spread over j's steps (c0/c1/c2),
// acc collapsed to range-reduced rsh at c3 so MMA pipe never waits on sin.
// SMEM map:
//   0      qb1s/2pi 1K | 1024 qw2s 3K | 4096 qb2s | 4224 fyh 2x512B
//   5248   part[64][4][3] f32 (3KB)
//   9216   B 128KB (4 x 32KB)
//   140288 fxs 32KB (64 rows x 512B linear)
//   173056 A 2 x 8KB
#define SM_QB1  0
#define SM_QW2  1024
#define SM_QB2  4096
#define SM_FYH  4224
#define SM_PART 5248
#define SM_B    9216
#define SM_FXS  140288
#define SM_A    173056
#define SMEM_TOTAL 189440

// sin(2*pi*r), r in [-0.5, 0.5]: Chebyshev deg-9 (err ~4.6e-6)
#define SB1 6.28909636f
#define SB3 -41.2476960f
#define SB5 80.0983142f
#define SB7 -70.2306714f
#define SB9 28.3901952f

__global__ __launch_bounds__(512, 1)
void fused_mma_kernel(
    const float* __restrict__ qb1, const float* __restrict__ qw2,
    const float* __restrict__ qb2, float* __restrict__ out)
{
    extern __shared__ __align__(1024) char smem[];
    const uint32_t sb = smem_u32(smem);
    const int tid = threadIdx.x;
    const int wid = tid >> 5;
    const int lane = tid & 31;
    const int wm = wid & 3;          // m-warp (16 rows each)
    const int wn = wid >> 2;         // n-warp (64 cols each)
    const int m0w = wm * 16;
    const int n0w = wn * 64;
    const int i0 = blockIdx.x * 64;
    const int j0 = blockIdx.y * 8;

    float* qb1s = (float*)(smem + SM_QB1);     // pre-scaled by 1/(2pi)
    float* qw2s = (float*)(smem + SM_QW2);
    float* qb2s = (float*)(smem + SM_QB2);
    uint32_t* fyhs = (uint32_t*)(smem + SM_FYH);
    float* part = (float*)(smem + SM_PART);

    // ---- async staging: group1 = fx tile + B chunk0; group2 = B chunks 1-3
    {
        uint32_t doff = (uint32_t)tid * 16;
        const char* fsrc = (const char*)(g_fxh + (size_t)i0 * HID);
#pragma unroll
        for (int e = 0; e < 4; e++)
            CP_ASYNC16(sb + SM_FXS + e * 8192 + doff, fsrc + e * 8192 + doff);
        const char* bsrc = (const char*)g_qpack;
#pragma unroll
        for (int e = 0; e < 4; e++)
            CP_ASYNC16(sb + SM_B + e * 8192 + doff, bsrc + e * 8192 + doff);
        CP_COMMIT();
#pragma unroll
        for (int e = 0; e < 12; e++)
            CP_ASYNC16(sb + SM_B + 32768 + e * 8192 + doff,
                       bsrc + 32768 + e * 8192 + doff);
        CP_COMMIT();
    }
    if (tid < 256) qb1s[tid] = qb1[tid] * 0.15915494309189535f;
    if (tid >= 256 && tid < 384)
        fyhs[tid - 256] = ((const uint32_t*)(g_fyh + (size_t)j0 * HID))[tid - 256];
    for (int e = tid; e < 3 * HID; e += 512) qw2s[e] = qw2[e];
    if (tid < 3) qb2s[tid] = qb2[tid];
    CP_WAIT1();                       // fx + B chunk0 landed
    __syncthreads();

    // ---- A build config: row rA = tid/8, 16B segment (tid&7) ----
    const int rA = tid >> 3;
    const uint32_t segB = (uint32_t)((tid & 7) << 4);   // byte col 0..112
    const uint32_t rowoffA = ((rA >> 3) << 10) + ((rA & 7) << 7);
    const uint32_t rxorA = (uint32_t)((rA & 7) << 4);
    const uint32_t fxrow = sb + SM_FXS + (uint32_t)rA * 512;

    auto build_A = [&](int c, int abuf, int fyb) {
        uint32_t srcoff = (uint32_t)(c * 128) + segB;
        uint4 f = *(const uint4*)(smem + (fxrow - sb) + srcoff);
        uint4 g = *(const uint4*)((char*)fyhs + fyb * 512 + srcoff);
        uint4 o;
        o.x = hmul2(f.x, g.x); o.y = hmul2(f.y, g.y);
        o.z = hmul2(f.z, g.z); o.w = hmul2(f.w, g.w);
        *(uint4*)(smem + SM_A + abuf * 8192 + rowoffA + (segB ^ rxorA)) = o;
    };

    // ---- LDSM per-thread components ----
    uint32_t rowA0, xorA0, colA, rowB[4], xorB[4], colB;
    {
        int r = m0w + (lane & 15);
        rowA0 = ((r >> 3) << 10) + ((r & 7) << 7);
        xorA0 = (uint32_t)((r & 7) << 4);
        colA = (uint32_t)((lane >> 4) << 4);
    }
    colB = (uint32_t)(((lane >> 3) & 1) << 4);
#pragma unroll
    for (int nb = 0; nb < 4; nb++) {
        int r = n0w + nb * 16 + (lane & 7) + ((lane >> 4) << 3);
        rowB[nb] = ((r >> 3) << 10) + ((r & 7) << 7);
        xorB[nb] = (uint32_t)((r & 7) << 4);
    }

    float acc[8][4];
#pragma unroll
    for (int nx = 0; nx < 8; nx++)
#pragma unroll
        for (int e = 0; e < 4; e++) acc[nx][e] = 0.f;
    u64t rsh[16];                      // range-reduced shadow (prev j)

    // ---- epilogue helpers ----
    auto epi_half = [&](int half) {
        const u64t B9 = dup2(SB9), B7 = dup2(SB7), B5 = dup2(SB5);
        const u64t B3 = dup2(SB3), B1 = dup2(SB1);
        u64t pr[6];
#pragma unroll
        for (int e = 0; e < 6; e++) pr[e] = pk2(0.f, 0.f);
#pragma unroll
        for (int q = 0; q < 4; q++) {
            int nx = half * 4 + q;
            int n = n0w + nx * 8 + (lane & 3) * 2;
            u64t w0 = *(const u64t*)(qw2s + n);
            u64t w1 = *(const u64t*)(qw2s + 256 + n);
            u64t w2 = *(const u64t*)(qw2s + 512 + n);
#pragma unroll
            for (int rh = 0; rh < 2; rh++) {
                u64t r2 = rsh[nx * 2 + rh];
                u64t s2 = f2mul(r2, r2);
                u64t p = f2fma(s2, B9, B7);
                p = f2fma(s2, p, B5);
                p = f2fma(s2, p, B3);
                p = f2fma(s2, p, B1);
                u64t h2 = f2mul(p, r2);
                pr[rh * 3 + 0] = f2fma(h2, w0, pr[rh * 3 + 0]);
                pr[rh * 3 + 1] = f2fma(h2, w1, pr[rh * 3 + 1]);
                pr[rh * 3 + 2] = f2fma(h2, w2, pr[rh * 3 + 2]);
            }
        }
        float ps[6];
#pragma unroll
        for (int e = 0; e < 6; e++) {
            float lo, hi;
            upk2(pr[e], lo, hi);
            ps[e] = lo + hi;
        }
#pragma unroll
        for (int d = 1; d <= 2; d <<= 1)
#pragma unroll
            for (int e = 0; e < 6; e++)
                ps[e] += __shfl_xor_sync(0xffffffffu, ps[e], d);
        if ((lane & 3) == 0) {
#pragma unroll
            for (int rh = 0; rh < 2; rh++) {
                int m = m0w + (lane >> 2) + rh * 8;
#pragma unroll
                for (int cc = 0; cc < 3; cc++) {
                    int idx = (m * 4 + wn) * 3 + cc;
                    if (half == 0) part[idx] = ps[rh * 3 + cc];
                    else part[idx] += ps[rh * 3 + cc];
                }
            }
        }
    };
    auto epi_out = [&](int pend) {
        if (tid < 192) {
            int m = tid & 63;
            int cc = tid >> 6;
            float s = qb2s[cc];
#pragma unroll
            for (int v = 0; v < 4; v++) s += part[(m * 4 + v) * 3 + cc];
            out[((unsigned)cc * W + (j0 + pend)) * H + i0 + m] =
                1.f / (1.f + __expf(-s));
        }
    };
    auto convert = [&]() {
        const u64t kInv  = dup2(0.15915494309189535f);
        const u64t kMag  = dup2(12582912.0f);
        const u64t kNMag = dup2(-12582912.0f);
        const u64t kN1   = dup2(-1.0f);
#pragma unroll
        for (int nx = 0; nx < 8; nx++) {
            int n = n0w + nx * 8 + (lane & 3) * 2;
            u64t b2 = *(const u64t*)(qb1s + n);
#pragma unroll
            for (int rh = 0; rh < 2; rh++) {
                u64t a2 = pk2(acc[nx][rh * 2], acc[nx][rh * 2 + 1]);
                u64t u2 = f2fma(a2, kInv, b2);
                u64t y2 = f2add(u2, kMag);
                u64t k2 = f2add(y2, kNMag);
                rsh[nx * 2 + rh] = f2fma(k2, kN1, u2);
            }
#pragma unroll
            for (int e = 0; e < 4; e++) acc[nx][e] = 0.f;
        }
    };

    // ---- prologue: build A(t=0) ----
    build_A(0, 0, 0);
    __syncthreads();

    // ---- flat pipeline: t = j*4 + c ----
    for (int t = 0; t < 32; t++) {
        const int jj = t >> 2;
        const int c = t & 3;

        if (c == 0 && jj < 7 && tid < 128)
            fyhs[((jj + 1) & 1) * 128 + tid] =
                ((const uint32_t*)(g_fyh + (size_t)(j0 + jj + 1) * HID))[tid];

        // MMA chunk c (A from buf t&1, B chunk c) — issue first
        {
            const uint32_t astg = sb + SM_A + (uint32_t)(t & 1) * 8192;
            const uint32_t bstg = sb + SM_B + (uint32_t)c * 32768;
#pragma unroll
            for (int s = 0; s < 4; s++) {
                const uint32_t ks = (uint32_t)(s * 32);
                uint32_t ah[4];
                ldsm_x4(ah, astg + rowA0 + ((colA + ks) ^ xorA0));
#pragma unroll
                for (int nb = 0; nb < 4; nb++) {
                    uint32_t bh[4];
                    ldsm_x4(bh, bstg + rowB[nb] + ((colB + ks) ^ xorB[nb]));
                    mma_f16(acc[nb * 2 + 0], ah, bh + 0);
                    mma_f16(acc[nb * 2 + 1], ah, bh + 2);
                }
            }
        }

        // build next A (overlaps in-flight MMAs)
        if (t < 31)
            build_A((t + 1) & 3, (t + 1) & 1, ((t + 1) >> 2) & 1);

        // spread epilogue of j-1 (overlaps in-flight MMAs)
        if (jj >= 1) {
            if (c == 0) epi_half(0);
            else if (c == 1) epi_half(1);
            else if (c == 2) epi_out(jj - 1);
        }

        // collapse acc -> rsh at end of j
        if (c == 3) convert();

        if (t == 0) CP_WAIT0();        // B chunks 1-3 visible after barrier
        __syncthreads();
    }

    // ---- tail: epilogue of j7 ----
    epi_half(0);
    epi_half(1);
    __syncthreads();
    epi_out(7);
}

// ---------------------------------------------------------------------------
extern "C" void kernel_launch(void* const* d_in, const int* in_sizes, int n_in,
                              void* d_out, int out_size)
{
    const float* x   = (const float*)d_in[0];
    const float* y   = (const float*)d_in[1];
    const float* bw0 = (const float*)d_in[2];
    const float* bb0 = (const float*)d_in[3];
    const float* bw1 = (const float*)d_in[4];
    const float* bb1 = (const float*)d_in[5];
    const float* pw1 = (const float*)d_in[6];
    const float* pb1 = (const float*)d_in[7];
    const float* pw2 = (const float*)d_in[8];
    const float* pb2 = (const float*)d_in[9];
    const float* qw1 = (const float*)d_in[10];
    const float* qb1 = (const float*)d_in[11];
    const float* qw2 = (const float*)d_in[12];
    const float* qb2 = (const float*)d_in[13];
    float* out = (float*)d_out;

    cudaFuncSetAttribute(fused_mma_kernel,
                         cudaFuncAttributeMaxDynamicSharedMemorySize, SMEM_TOTAL);

    pack_qw1_kernel<<<128, 256>>>(qw1);
    branch_kernel<<<dim3(H / 16, 2), 256>>>(x, y, bw0, bb0, bw1, bb1,
                                            pw1, pb1, pw2, pb2);
    fused_mma_kernel<<<dim3(16, 128), 512, SMEM_TOTAL>>>(qb1, qw2, qb2, out);
}

// round 11
// speedup vs baseline: 1.4897x; 1.4897x over previous
#include <cuda_runtime.h>
#include <cuda_bf16.h>
#include <cuda_fp16.h>
#include <cstdint>

#define H 1024
#define W 1024
#define HID 256
#define C 3

typedef unsigned long long u64t;

// ---------------------------------------------------------------------------
// global scratch
// ---------------------------------------------------------------------------
__device__ __align__(16) __half g_fxh[H * HID];
__device__ __align__(16) __half g_fyh[W * HID];
// qw1 as fp16, SW128-swizzled K-major tiles. chunk c (k0=64c): 32KB at c*32768
__device__ __align__(16) unsigned char g_qpack[4 * 32768];

// ---------------- fast sine (scalar, branch kernel) ------------------------
__device__ __forceinline__ float fast_sin(float x) {
    const float INV_PI = 0.318309886183790671f;
    float k = rintf(x * INV_PI);
    float r = fmaf(-k, 3.14159274101257324f, x);
    r = fmaf(k, 8.74227765734758577e-8f, r);
    float s = r * r;
    float p = fmaf(s, 2.75573192e-6f, -1.98412698e-4f);
    p = fmaf(s, p, 8.33333333e-3f);
    p = fmaf(s, p, -1.66666667e-1f);
    float res = fmaf(s * r, p, r);
    int ki = (int)k;
    return (ki & 1) ? -res : res;
}

// ---------------- f32x2 packed helpers -------------------------------------
__device__ __forceinline__ u64t pk2(float lo, float hi) {
    u64t r;
    asm("mov.b64 %0, {%1, %2};" : "=l"(r)
        : "r"(__float_as_uint(lo)), "r"(__float_as_uint(hi)));
    return r;
}
__device__ __forceinline__ void upk2(u64t v, float& lo, float& hi) {
    uint32_t a, b;
    asm("mov.b64 {%0, %1}, %2;" : "=r"(a), "=r"(b) : "l"(v));
    lo = __uint_as_float(a);
    hi = __uint_as_float(b);
}
__device__ __forceinline__ u64t f2fma(u64t a, u64t b, u64t c) {
    u64t r;
    asm("fma.rn.f32x2 %0, %1, %2, %3;" : "=l"(r) : "l"(a), "l"(b), "l"(c));
    return r;
}

// ---------------- misc PTX helpers -----------------------------------------
__device__ __forceinline__ uint32_t smem_u32(const void* p) {
    uint32_t a;
    asm("{ .reg .u64 t; cvta.to.shared.u64 t, %1; cvt.u32.u64 %0, t; }"
        : "=r"(a) : "l"(p));
    return a;
}
__device__ __forceinline__ void ldsm_x4(uint32_t* r, uint32_t addr) {
    asm volatile("ldmatrix.sync.aligned.m8n8.x4.shared.b16 {%0,%1,%2,%3}, [%4];"
                 : "=r"(r[0]), "=r"(r[1]), "=r"(r[2]), "=r"(r[3]) : "r"(addr));
}
__device__ __forceinline__ void mma_f16(float* c, const uint32_t* a,
                                        const uint32_t* b) {
    asm volatile(
        "mma.sync.aligned.m16n8k16.row.col.f32.f16.f16.f32 "
        "{%0,%1,%2,%3}, {%4,%5,%6,%7}, {%8,%9}, {%0,%1,%2,%3};"
        : "+f"(c[0]), "+f"(c[1]), "+f"(c[2]), "+f"(c[3])
        : "r"(a[0]), "r"(a[1]), "r"(a[2]), "r"(a[3]), "r"(b[0]), "r"(b[1]));
}
#define CP_ASYNC16(dst, src) \
    asm volatile("cp.async.cg.shared.global [%0], [%1], 16;" \
                 :: "r"(dst), "l"(src))
#define CP_COMMIT()  asm volatile("cp.async.commit_group;")
#define CP_WAIT0()   asm volatile("cp.async.wait_group 0;" ::: "memory")

__device__ __forceinline__ uint32_t packh2(float hi, float lo) {
    uint32_t r;
    asm("cvt.rn.f16x2.f32 %0, %1, %2;" : "=r"(r) : "f"(hi), "f"(lo));
    return r;
}
__device__ __forceinline__ uint32_t hmul2(uint32_t a, uint32_t b) {
    uint32_t r;
    asm("mul.rn.f16x2 %0, %1, %2;" : "=r"(r) : "r"(a), "r"(b));
    return r;
}

// ---------------- kernel 0: pack+swizzle qw1 to fp16 -----------------------
__global__ void pack_qw1_kernel(const float* __restrict__ qw1) {
    int idx = blockIdx.x * 256 + threadIdx.x;
    int n = idx >> 7;
    int kw = idx & 127;
    int k = kw * 2;
    int cch = k >> 6;
    int kk = k & 63;
    float w0 = qw1[n * HID + k];
    float w1 = qw1[n * HID + k + 1];
    uint32_t hw = packh2(w1, w0);
    uint32_t off = ((n >> 3) << 10) + ((n & 7) << 7) + kk * 2;
    uint32_t sw = off ^ ((off >> 3) & 0x70);
    *(uint32_t*)(g_qpack + cch * 32768 + sw) = hw;
}

// ---------------- kernel 1: branch + premerge (fp16 outputs) ---------------
__device__ __forceinline__ void dense_layer(
    const float (*hin)[HID], float (*hout)[HID],
    const float* __restrict__ pw, const float* __restrict__ pb, int t)
{
    float acc[16];
    float bias = pb[t];
#pragma unroll
    for (int r = 0; r < 16; r++) acc[r] = bias;
    const float4* pw4 = (const float4*)pw;
#pragma unroll 4
    for (int k4 = 0; k4 < HID / 4; k4++) {
        float4 w4 = pw4[t * (HID / 4) + k4];
#pragma unroll
        for (int r = 0; r < 16; r++) {
            float4 hv = *(const float4*)&hin[r][k4 * 4];
            acc[r] = fmaf(hv.x, w4.x, acc[r]);
            acc[r] = fmaf(hv.y, w4.y, acc[r]);
            acc[r] = fmaf(hv.z, w4.z, acc[r]);
            acc[r] = fmaf(hv.w, w4.w, acc[r]);
        }
    }
#pragma unroll
    for (int r = 0; r < 16; r++) hout[r][t] = fast_sin(acc[r]);
}

__global__ void branch_kernel(
    const float* __restrict__ x, const float* __restrict__ y,
    const float* __restrict__ bw0, const float* __restrict__ bb0,
    const float* __restrict__ bw1, const float* __restrict__ bb1,
    const float* __restrict__ pw1, const float* __restrict__ pb1,
    const float* __restrict__ pw2, const float* __restrict__ pb2)
{
    int axis = blockIdx.y;
    const float* coord = axis ? y : x;
    const float* bw = axis ? bw1 : bw0;
    const float* bb = axis ? bb1 : bb0;
    __half* outf = axis ? g_fyh : g_fxh;
    int r0 = blockIdx.x * 16;
    int t = threadIdx.x;

    __shared__ __align__(16) float hA[16][HID];
    __shared__ __align__(16) float hB[16][HID];

    float w = bw[t], b = bb[t];
#pragma unroll
    for (int r = 0; r < 16; r++)
        hA[r][t] = fast_sin(fmaf(coord[r0 + r], w, b));
    __syncthreads();
    dense_layer(hA, hB, pw1, pb1, t);
    __syncthreads();
    dense_layer(hB, hA, pw2, pb2, t);
    __syncthreads();
#pragma unroll
    for (int r = 0; r < 16; r++)
        outf[(r0 + r) * HID + t] = __float2half_rn(hA[r][t]);
}

// ---------------- kernel 2: M=128, B-resident, MUFU epilogue ---------------
// grid (8, 128): i0 = bx*128, j in [by*8, by*8+8). 512 threads = 16 warps
// (4M x 4N), warp tile 32x64. A quad-buffered, __syncthreads every 2 steps.
// SMEM map:
//   0      qb1s 1K | 1024 qw2s 3K | 4096 qb2s | 4608 fyh 2x512B
//   5632   part[128][4][3] f32 (6KB)
//   13312  B 128KB (4 x 32KB)
//   144384 A 4 x 16KB
#define SM_QB1  0
#define SM_QW2  1024
#define SM_QB2  4096
#define SM_FYH  4608
#define SM_PART 5632
#define SM_B    13312
#define SM_A    144384
#define SMEM_TOTAL 209920

__global__ __launch_bounds__(512, 1)
void fused_mma_kernel(
    const float* __restrict__ qb1, const float* __restrict__ qw2,
    const float* __restrict__ qb2, float* __restrict__ out)
{
    extern __shared__ __align__(1024) char smem[];
    const uint32_t sb = smem_u32(smem);
    const int tid = threadIdx.x;
    const int wid = tid >> 5;
    const int lane = tid & 31;
    const int wm = wid & 3;
    const int wn = wid >> 2;
    const int m0w = wm * 32;
    const int n0w = wn * 64;
    const int i0 = blockIdx.x * 128;
    const int j0 = blockIdx.y * 8;

    float* qb1s = (float*)(smem + SM_QB1);
    float* qw2s = (float*)(smem + SM_QW2);
    float* qb2s = (float*)(smem + SM_QB2);
    uint32_t* fyhs = (uint32_t*)(smem + SM_FYH);   // 2 buffers x 128 h2 words
    float* part = (float*)(smem + SM_PART);

    // ---- one-time staging: B via cp.async, smalls, fyh(j0) ----
    {
        const char* src = (const char*)g_qpack;
        uint32_t dst = sb + SM_B;
#pragma unroll
        for (int e = 0; e < 16; e++) {
            uint32_t off = (uint32_t)(e * 512 + tid) * 16;
            CP_ASYNC16(dst + off, src + off);
        }
        CP_COMMIT();
    }
    if (tid < 256) qb1s[tid] = qb1[tid];
    if (tid >= 256 && tid < 384)
        fyhs[tid - 256] = ((const uint32_t*)(g_fyh + (size_t)j0 * HID))[tid - 256];
    for (int e = tid; e < 3 * HID; e += 512) qw2s[e] = qw2[e];
    if (tid < 3) qb2s[tid] = qb2[tid];
    __syncthreads();          // fyhs/qb1s/qw2s visible before any A-build

    // ---- A build config: row rA = tid/4, k-quarter kq ----
    const int rA = tid >> 2;
    const int kq = (tid & 3) << 4;             // k offset within 64-chunk
    const uint32_t rowoff = ((rA >> 3) << 10) + ((rA & 7) << 7);
    const uint32_t rxor = (rA & 7) << 4;

    uint4 pf0, pf1;                            // prefetched fx fp16 (16 halves)
    auto load_pf = [&](int c) {
        const uint4* p = (const uint4*)(g_fxh + (size_t)(i0 + rA) * HID + c * 64 + kq);
        pf0 = p[0];
        pf1 = p[1];
    };
    auto build_A_pf = [&](int abuf, int fyb, int c) {
        const uint4* fyp = (const uint4*)((char*)fyhs + fyb * 512 + (c * 64 + kq) * 2);
        uint4 g0 = fyp[0], g1 = fyp[1];
        uint32_t hw[8];
        hw[0] = hmul2(pf0.x, g0.x); hw[1] = hmul2(pf0.y, g0.y);
        hw[2] = hmul2(pf0.z, g0.z); hw[3] = hmul2(pf0.w, g0.w);
        hw[4] = hmul2(pf1.x, g1.x); hw[5] = hmul2(pf1.y, g1.y);
        hw[6] = hmul2(pf1.z, g1.z); hw[7] = hmul2(pf1.w, g1.w);
        char* base = smem + SM_A + abuf * 16384;
        uint32_t c0 = (uint32_t)(kq * 2);
        uint32_t o0 = rowoff + (c0 ^ rxor);
        uint32_t o1 = rowoff + ((c0 + 16) ^ rxor);
        *(uint4*)(base + o0) = make_uint4(hw[0], hw[1], hw[2], hw[3]);
        *(uint4*)(base + o1) = make_uint4(hw[4], hw[5], hw[6], hw[7]);
    };

    // ---- LDSM per-thread row/col components ----
    uint32_t rowA[2], xorA[2], colA;
    uint32_t rowB[4], xorB[4], colB;
    colA = (uint32_t)((lane >> 4) << 4);
#pragma unroll
    for (int mb = 0; mb < 2; mb++) {
        int r = m0w + mb * 16 + (lane & 15);
        rowA[mb] = ((r >> 3) << 10) + ((r & 7) << 7);
        xorA[mb] = (uint32_t)((r & 7) << 4);
    }
    colB = (uint32_t)(((lane >> 3) & 1) << 4);
#pragma unroll
    for (int nb = 0; nb < 4; nb++) {
        int r = n0w + nb * 16 + (lane & 7) + ((lane >> 4) << 3);
        rowB[nb] = ((r >> 3) << 10) + ((r & 7) << 7);
        xorB[nb] = (uint32_t)((r & 7) << 4);
    }

    float acc[2][8][4];
#pragma unroll
    for (int mb = 0; mb < 2; mb++)
#pragma unroll
        for (int nx = 0; nx < 8; nx++)
#pragma unroll
            for (int e = 0; e < 4; e++) acc[mb][nx][e] = 0.f;

    // prologue: build A for t=0 (chunk0) and t=1 (chunk1); prefetch chunk2.
    load_pf(0);
    build_A_pf(0, 0, 0);
    load_pf(1);
    build_A_pf(1, 0, 1);
    load_pf(2);
    CP_WAIT0();                        // all B chunks landed
    __syncthreads();

    // ---- flat pipeline: t = j*4 + c ; sync every 2 steps ----
    for (int t = 0; t < 32; t++) {
        const int jj = t >> 2;
        const int c = t & 3;

        if (c == 0) {
            // final output store for j-1 (part synced at end of t-1)
            if (jj >= 1 && tid < 384) {
                int m = tid & 127;
                int cc = tid >> 7;
                float s = qb2s[cc];
#pragma unroll
                for (int v = 0; v < 4; v++) s += part[(m * 4 + v) * 3 + cc];
                out[((unsigned)cc * W + (j0 + jj - 1)) * H + i0 + m] =
                    1.f / (1.f + __expf(-s));
            }
            if (jj < 7 && tid < 128)
                fyhs[((jj + 1) & 1) * 128 + tid] =
                    ((const uint32_t*)(g_fyh + (size_t)(j0 + jj + 1) * HID))[tid];
        }

        // MMA chunk c: A from buf t&3, B chunk at SM_B + c*32KB
        {
            const uint32_t astg = sb + SM_A + (uint32_t)(t & 3) * 16384;
            const uint32_t bstg = sb + SM_B + (uint32_t)c * 32768;
#pragma unroll
            for (int s = 0; s < 4; s++) {
                const uint32_t ks = (uint32_t)(s * 32);
                uint32_t ah[2][4];
#pragma unroll
                for (int mb = 0; mb < 2; mb++)
                    ldsm_x4(ah[mb], astg + rowA[mb] + ((colA + ks) ^ xorA[mb]));
#pragma unroll
                for (int nb = 0; nb < 4; nb++) {
                    uint32_t bh[4];
                    ldsm_x4(bh, bstg + rowB[nb] + ((colB + ks) ^ xorB[nb]));
#pragma unroll
                    for (int mb = 0; mb < 2; mb++) {
                        mma_f16(acc[mb][nb * 2 + 0], ah[mb], bh + 0);
                        mma_f16(acc[mb][nb * 2 + 1], ah[mb], bh + 2);
                    }
                }
            }
        }

        // build A for t+2 from prefetched regs; prefetch for t+3
        if (t < 30)
            build_A_pf((t + 2) & 3, ((t + 2) >> 2) & 1, (t + 2) & 3);
        if (t < 29)
            load_pf((t + 3) & 3);

        // ---- epilogue at end of each j: bias + MUFU sin + f32x2 GEMV ----
        if (c == 3) {
            u64t pr[12];
#pragma unroll
            for (int e = 0; e < 12; e++) pr[e] = pk2(0.f, 0.f);
#pragma unroll
            for (int mb = 0; mb < 2; mb++) {
#pragma unroll
                for (int nx = 0; nx < 8; nx++) {
                    int n = n0w + nx * 8 + (lane & 3) * 2;
                    float b0 = qb1s[n], b1 = qb1s[n + 1];
                    u64t w0 = *(const u64t*)(qw2s + n);
                    u64t w1 = *(const u64t*)(qw2s + 256 + n);
                    u64t w2 = *(const u64t*)(qw2s + 512 + n);
#pragma unroll
                    for (int rh = 0; rh < 2; rh++) {
                        float s0 = acc[mb][nx][rh * 2] + b0;
                        float s1 = acc[mb][nx][rh * 2 + 1] + b1;
                        acc[mb][nx][rh * 2] = 0.f;
                        acc[mb][nx][rh * 2 + 1] = 0.f;
                        float h0 = __sinf(s0);
                        float h1 = __sinf(s1);
                        u64t h2 = pk2(h0, h1);
                        int slot = (mb * 2 + rh) * 3;
                        pr[slot + 0] = f2fma(h2, w0, pr[slot + 0]);
                        pr[slot + 1] = f2fma(h2, w1, pr[slot + 1]);
                        pr[slot + 2] = f2fma(h2, w2, pr[slot + 2]);
                    }
                }
            }
            float p[12];
#pragma unroll
            for (int e = 0; e < 12; e++) {
                float lo, hi;
                upk2(pr[e], lo, hi);
                p[e] = lo + hi;
            }
#pragma unroll
            for (int d = 1; d <= 2; d <<= 1)
#pragma unroll
                for (int e = 0; e < 12; e++)
                    p[e] += __shfl_xor_sync(0xffffffffu, p[e], d);

            if ((lane & 3) == 0) {
#pragma unroll
                for (int mb = 0; mb < 2; mb++)
#pragma unroll
                    for (int rh = 0; rh < 2; rh++) {
                        int m = m0w + mb * 16 + (lane >> 2) + rh * 8;
#pragma unroll
                        for (int cc = 0; cc < 3; cc++)
                            part[(m * 4 + wn) * 3 + cc] = p[(mb * 2 + rh) * 3 + cc];
                    }
            }
        }

        if (t & 1) __syncthreads();
    }

    // ---- tail: output for j7 (part synced by loop's final barrier) ----
    if (tid < 384) {
        int m = tid & 127;
        int cc = tid >> 7;
        float s = qb2s[cc];
#pragma unroll
        for (int v = 0; v < 4; v++) s += part[(m * 4 + v) * 3 + cc];
        out[((unsigned)cc * W + (j0 + 7)) * H + i0 + m] =
            1.f / (1.f + __expf(-s));
    }
}

// ---------------------------------------------------------------------------
extern "C" void kernel_launch(void* const* d_in, const int* in_sizes, int n_in,
                              void* d_out, int out_size)
{
    const float* x   = (const float*)d_in[0];
    const float* y   = (const float*)d_in[1];
    const float* bw0 = (const float*)d_in[2];
    const float* bb0 = (const float*)d_in[3];
    const float* bw1 = (const float*)d_in[4];
    const float* bb1 = (const float*)d_in[5];
    const float* pw1 = (const float*)d_in[6];
    const float* pb1 = (const float*)d_in[7];
    const float* pw2 = (const float*)d_in[8];
    const float* pb2 = (const float*)d_in[9];
    const float* qw1 = (const float*)d_in[10];
    const float* qb1 = (const float*)d_in[11];
    const float* qw2 = (const float*)d_in[12];
    const float* qb2 = (const float*)d_in[13];
    float* out = (float*)d_out;

    cudaFuncSetAttribute(fused_mma_kernel,
                         cudaFuncAttributeMaxDynamicSharedMemorySize, SMEM_TOTAL);

    pack_qw1_kernel<<<128, 256>>>(qw1);
    branch_kernel<<<dim3(H / 16, 2), 256>>>(x, y, bw0, bb0, bw1, bb1,
                                            pw1, pb1, pw2, pb2);
    fused_mma_kernel<<<dim3(8, 128), 512, SMEM_TOTAL>>>(qb1, qw2, qb2, out);
}